// round 1
// baseline (speedup 1.0000x reference)
#include <cuda_runtime.h>
#include <cstdint>

#define BB 8
#define NN 4096
#define NP (BB*NN)
#define KK 20

// ---------------- scratch (static device allocations; no cudaMalloc) -------------
__device__ float d_h[NP*64];
__device__ float d_hsq[NP];
__device__ float d_xsq[NP];
__device__ int   d_idx1[NP*KK];
__device__ int   d_idx2[NP*KK];
__device__ float d_A1[NP*128];
__device__ float d_C1[NP*128];
__device__ float d_cat[(size_t)NP*512];   // x1 | x2 | x3
__device__ float d_A3[(size_t)NP*256];
__device__ float d_C3[(size_t)NP*256];
__device__ float d_w3t[512*1024];

// ---------------- kernel 1: 3->64->64 MLP + squared norms ------------------------
__global__ __launch_bounds__(256) void mlp_kernel(
    const float* __restrict__ x, const float* __restrict__ w1, const float* __restrict__ b1,
    const float* __restrict__ w2, const float* __restrict__ b2)
{
    __shared__ float w1s[192], b1s[64], b2s[64], w2s[4096];
    int t = threadIdx.x;
    for (int i = t; i < 192; i += 256) w1s[i] = w1[i];
    if (t < 64) { b1s[t] = b1[t]; b2s[t] = b2[t]; }
    for (int i = t; i < 4096; i += 256) w2s[i] = w2[i];
    __syncthreads();
    int pt = blockIdx.x * 256 + t;
    float x0 = x[pt*3+0], x1 = x[pt*3+1], x2 = x[pt*3+2];
    d_xsq[pt] = x0*x0 + x1*x1 + x2*x2;
    float h1[64];
#pragma unroll
    for (int o = 0; o < 64; o++) {
        float a = b1s[o] + w1s[o*3]*x0 + w1s[o*3+1]*x1 + w1s[o*3+2]*x2;
        h1[o] = fmaxf(a, 0.f);
    }
    float sq = 0.f;
#pragma unroll 2
    for (int o = 0; o < 64; o++) {
        float a = b2s[o];
#pragma unroll
        for (int c = 0; c < 64; c++) a += w2s[o*64+c] * h1[c];
        a = fmaxf(a, 0.f);
        d_h[(size_t)pt*64 + o] = a;
        sq += a*a;
    }
    d_hsq[pt] = sq;
}

// ---------------- kernel 2: KNN (warp per query, top-20) -------------------------
// dist = 2*dot(q,c) - |q|^2 - |c|^2 ; keep 20 largest; tie-break smaller index.
template<int C, int CP>
__global__ __launch_bounds__(1024) void knn_kernel(
    const float* __restrict__ data, const float* __restrict__ sq, int* __restrict__ out)
{
    const int TC = 128;
    __shared__ float cs[TC*CP];
    __shared__ float cxx[TC];
    __shared__ float qs[32*CP];
    __shared__ float qxx_s[32];
    int b  = blockIdx.x / (NN/32);
    int q0 = (blockIdx.x % (NN/32)) * 32;
    int t = threadIdx.x, warp = t >> 5, lane = t & 31;
    for (int i = t; i < 32*C; i += 1024) {
        int qq = i / C, d = i - qq*C;
        qs[qq*CP + d] = data[((size_t)(b*NN + q0 + qq))*C + d];
    }
    if (t < 32) qxx_s[t] = sq[b*NN + q0 + t];
    __syncthreads();
    float qxx = qxx_s[warp];
    float vals[KK]; int ids[KK];
#pragma unroll
    for (int r = 0; r < KK; r++) { vals[r] = -3.4e38f; ids[r] = 0x7fffffff; }
    float minv = -3.4e38f; int minp = 0;

    for (int tile = 0; tile < NN/TC; tile++) {
        __syncthreads();
        for (int i = t; i < TC*C; i += 1024) {
            int r = i / C, d = i - r*C;
            cs[r*CP + d] = data[((size_t)(b*NN + tile*TC + r))*C + d];
        }
        if (t < TC) cxx[t] = sq[b*NN + tile*TC + t];
        __syncthreads();
#pragma unroll
        for (int ii = 0; ii < TC/32; ii++) {
            int cl = ii*32 + lane;
            float dot = 0.f;
#pragma unroll
            for (int d = 0; d < C; d++) dot += qs[warp*CP + d] * cs[cl*CP + d];
            float dist = 2.f*dot - qxx - cxx[cl];
            if (dist > minv) {
                vals[minp] = dist; ids[minp] = tile*TC + cl;
                minv = vals[0]; minp = 0;
#pragma unroll
                for (int r = 1; r < KK; r++) if (vals[r] < minv) { minv = vals[r]; minp = r; }
            }
        }
    }
    // sort lane-local list desc by (val, idx asc)
#pragma unroll 1
    for (int i = 1; i < KK; i++) {
        float v = vals[i]; int id = ids[i]; int j = i - 1;
        while (j >= 0 && (vals[j] < v || (vals[j] == v && ids[j] > id))) {
            vals[j+1] = vals[j]; ids[j+1] = ids[j]; j--;
        }
        vals[j+1] = v; ids[j+1] = id;
    }
    // warp merge: 20 rounds of argmax over lane heads
    int ptr = 0;
    int q = q0 + warp;
#pragma unroll 1
    for (int r = 0; r < KK; r++) {
        float v = (ptr < KK) ? vals[ptr] : -3.4e38f;
        int  id = (ptr < KK) ? ids[ptr]  : 0x7fffffff;
        int  wl = lane;
#pragma unroll
        for (int off = 16; off; off >>= 1) {
            float ov = __shfl_xor_sync(0xffffffffu, v, off);
            int  oid = __shfl_xor_sync(0xffffffffu, id, off);
            int  owl = __shfl_xor_sync(0xffffffffu, wl, off);
            if (ov > v || (ov == v && oid < id)) { v = ov; id = oid; wl = owl; }
        }
        if (lane == wl) ptr++;
        if (lane == 0) out[((size_t)(b*NN + q))*KK + r] = id;
    }
}

// ---------------- kernel 3: precompute A = Wa*in, C = (Wb-Wa)*in + bias ----------
// W is (Cout, 2*Cin): cols [0,Cin) multiply (nbr-ctr), cols [Cin,2Cin) multiply ctr.
template<int CIN>
__global__ __launch_bounds__(128) void precomp_kernel(
    const float* __restrict__ in, int instride, int inoff,
    const float* __restrict__ W, const float* __restrict__ bias,
    float* __restrict__ A, float* __restrict__ Cc, int Cout)
{
    extern __shared__ float sm[];
    float* wa = sm;               // [CIN][128]
    float* wd = sm + CIN*128;     // [CIN][128]  (= Wb - Wa)
    __shared__ float inv[4*CIN];
    int t = threadIdx.x;
    int o0 = blockIdx.y * 128;
    int o  = o0 + t;
    // coalesced load of this block's 128 weight rows
    for (int i = t; i < 128*2*CIN; i += 128) {
        int oo = i / (2*CIN), c = i - oo*(2*CIN);
        float v = W[(size_t)o0*2*CIN + i];
        if (c < CIN) wa[c*128 + oo] = v; else wd[(c-CIN)*128 + oo] = v;
    }
    __syncthreads();
    for (int c = 0; c < CIN; c++) wd[c*128 + t] -= wa[c*128 + t];
    float bo = bias[o];
    __syncthreads();

    int ppb = NP / gridDim.x;
    int pt0 = blockIdx.x * ppb;
    for (int g = 0; g < ppb; g += 4) {
        __syncthreads();
        for (int i = t; i < 4*CIN; i += 128) {
            int p = i / CIN, c = i - p*CIN;
            inv[i] = in[(size_t)(pt0 + g + p)*instride + inoff + c];
        }
        __syncthreads();
        float a0=0,a1=0,a2=0,a3=0, c0=bo,c1=bo,c2=bo,c3=bo;
        for (int c = 0; c < CIN; c++) {
            float va = wa[c*128 + t], vd = wd[c*128 + t];
            float v0 = inv[c], v1 = inv[CIN+c], v2 = inv[2*CIN+c], v3 = inv[3*CIN+c];
            a0 += va*v0; a1 += va*v1; a2 += va*v2; a3 += va*v3;
            c0 += vd*v0; c1 += vd*v1; c2 += vd*v2; c3 += vd*v3;
        }
        A [(size_t)(pt0+g+0)*Cout + o] = a0;  Cc[(size_t)(pt0+g+0)*Cout + o] = c0;
        A [(size_t)(pt0+g+1)*Cout + o] = a1;  Cc[(size_t)(pt0+g+1)*Cout + o] = c1;
        A [(size_t)(pt0+g+2)*Cout + o] = a2;  Cc[(size_t)(pt0+g+2)*Cout + o] = c2;
        A [(size_t)(pt0+g+3)*Cout + o] = a3;  Cc[(size_t)(pt0+g+3)*Cout + o] = c3;
    }
}

// ---------------- kernel 4: fused edge-conv1 (decomposed) + edge-conv2 GEMV ------
__global__ __launch_bounds__(128) void edge2_kernel(
    const float* __restrict__ A1, const float* __restrict__ C1,
    const int* __restrict__ idx, const float* __restrict__ w2,
    const float* __restrict__ b2, float* __restrict__ cat)
{
    extern __shared__ float sm[];
    float* ws  = sm;                  // [128][132] padded (16B aligned rows)
    float* gs  = sm + 128*132;        // [40][128]  g for 2 points x 20 nbrs
    float* c1s = gs + 40*128;         // [2][128]
    float* b2s = c1s + 256;           // [128]
    int*   ixs = (int*)(b2s + 128);   // [40]
    int t = threadIdx.x;
    for (int i = t; i < 128*128; i += 128) { int o = i >> 7, c = i & 127; ws[o*132 + c] = w2[i]; }
    b2s[t] = b2[t];
    __syncthreads();

    int ppb = (NP/2) / gridDim.x;
    for (int pr = 0; pr < ppb; pr++) {
        int pt0 = (blockIdx.x * ppb + pr) * 2;
        __syncthreads();
        c1s[t]       = C1[(size_t)pt0*128 + t];
        c1s[128 + t] = C1[(size_t)(pt0+1)*128 + t];
        if (t < 40) { int p = t / 20, k = t - p*20; ixs[t] = idx[(size_t)(pt0+p)*KK + k]; }
        __syncthreads();
        int b = pt0 / NN;
        float x1a = -3.4e38f, x1b = -3.4e38f;
        for (int pk = 0; pk < 40; pk++) {
            int nbr = ixs[pk];
            float a = A1[((size_t)(b*NN + nbr))*128 + t];
            float v = fmaxf(a + c1s[(pk >= 20 ? 128 : 0) + t], 0.f);
            gs[pk*128 + t] = v;
            if (pk < 20) x1a = fmaxf(x1a, v); else x1b = fmaxf(x1b, v);
        }
        __syncthreads();
        float acc[40];
#pragma unroll
        for (int i = 0; i < 40; i++) acc[i] = b2s[t];
#pragma unroll 1
        for (int c4 = 0; c4 < 32; c4++) {
            float4 wv = *(const float4*)&ws[t*132 + c4*4];
#pragma unroll
            for (int pk = 0; pk < 40; pk++) {
                float4 gv = *(const float4*)&gs[pk*128 + c4*4];
                acc[pk] += wv.x*gv.x + wv.y*gv.y + wv.z*gv.z + wv.w*gv.w;
            }
        }
        float m0 = -3.4e38f, m1 = -3.4e38f;
#pragma unroll
        for (int k = 0; k < 20; k++) { m0 = fmaxf(m0, acc[k]); m1 = fmaxf(m1, acc[20+k]); }
        cat[(size_t)pt0*512 + t]             = x1a;
        cat[(size_t)pt0*512 + 128 + t]       = fmaxf(m0, 0.f);
        cat[(size_t)(pt0+1)*512 + t]         = x1b;
        cat[(size_t)(pt0+1)*512 + 128 + t]   = fmaxf(m1, 0.f);
    }
}

// ---------------- kernel 5: edge-conv3 (fully decomposed: gather+add+max) --------
__global__ __launch_bounds__(256) void edge3_kernel(
    const float* __restrict__ A3, const float* __restrict__ C3,
    const int* __restrict__ idx, float* __restrict__ cat)
{
    __shared__ float c3s[256];
    __shared__ int ixs[KK];
    int t = threadIdx.x;
    int ppb = NP / gridDim.x;
    for (int g = 0; g < ppb; g++) {
        int pt = blockIdx.x * ppb + g;
        __syncthreads();
        c3s[t] = C3[(size_t)pt*256 + t];
        if (t < KK) ixs[t] = idx[(size_t)pt*KK + t];
        __syncthreads();
        int b = pt / NN;
        float m = -3.4e38f;
#pragma unroll 4
        for (int k = 0; k < KK; k++) {
            float a = A3[((size_t)(b*NN + ixs[k]))*256 + t];
            m = fmaxf(m, a + c3s[t]);
        }
        cat[(size_t)pt*512 + 256 + t] = fmaxf(m, 0.f);
    }
}

// ---------------- kernel 6: weight transpose for final GEMM ----------------------
__global__ __launch_bounds__(256) void transpose_w3(const float* __restrict__ w3, float* __restrict__ w3t)
{
    int i = blockIdx.x * 256 + threadIdx.x;   // 512*1024 elements
    int o = i >> 9, c = i & 511;
    w3t[c*1024 + o] = w3[i];
}

// ---------------- kernel 7: final 1024x512 GEMM + relu, channel-major output -----
__global__ __launch_bounds__(256) void fgemm_kernel(
    const float* __restrict__ cat, const float* __restrict__ w3t,
    const float* __restrict__ b3, float* __restrict__ out)
{
    extern __shared__ float sm[];
    float* Ws = sm;             // [64][256]
    float* Xs = sm + 64*256;    // [64][68] padded
    int t = threadIdx.x;
    int o0 = blockIdx.y * 256;
    int n0 = blockIdx.x * 64;
    float acc[64];
    float bo = b3[o0 + t];
#pragma unroll
    for (int p = 0; p < 64; p++) acc[p] = bo;
    for (int kc = 0; kc < 512; kc += 64) {
        __syncthreads();
        for (int i = t; i < 64*256; i += 256) { int k = i >> 8, o = i & 255; Ws[k*256 + o] = w3t[(size_t)(kc + k)*1024 + o0 + o]; }
        for (int i = t; i < 64*64; i += 256)  { int p = i >> 6, k = i & 63;  Xs[k*68 + p] = cat[(size_t)(n0 + p)*512 + kc + k]; }
        __syncthreads();
#pragma unroll 1
        for (int k = 0; k < 64; k++) {
            float w = Ws[k*256 + t];
#pragma unroll
            for (int p4 = 0; p4 < 16; p4++) {
                float4 xv = *(const float4*)&Xs[k*68 + p4*4];
                acc[p4*4+0] += w*xv.x;
                acc[p4*4+1] += w*xv.y;
                acc[p4*4+2] += w*xv.z;
                acc[p4*4+3] += w*xv.w;
            }
        }
    }
    // stage to smem and write coalesced in channel-major layout (B,1024,N)
    __syncthreads();
    float* stage = sm;   // [256][65]
#pragma unroll
    for (int p = 0; p < 64; p++) stage[t*65 + p] = fmaxf(acc[p], 0.f);
    __syncthreads();
    int b = n0 / NN; int n = n0 - b*NN;
    for (int i = t; i < 256*64; i += 256) {
        int o = i >> 6, p = i & 63;
        out[((size_t)(b*1024 + o0 + o))*NN + n + p] = stage[o*65 + p];
    }
}

// ---------------------------------------------------------------------------------
extern "C" void kernel_launch(void* const* d_in, const int* in_sizes, int n_in,
                              void* d_out, int out_size)
{
    const float* x    = (const float*)d_in[0];
    const float* w1   = (const float*)d_in[1];
    const float* b1   = (const float*)d_in[2];
    const float* w2   = (const float*)d_in[3];
    const float* b2   = (const float*)d_in[4];
    const float* wdg1 = (const float*)d_in[5];
    const float* bdg1 = (const float*)d_in[6];
    const float* wdg2 = (const float*)d_in[7];
    const float* bdg2 = (const float*)d_in[8];
    const float* wsn1 = (const float*)d_in[9];
    const float* bsn1 = (const float*)d_in[10];
    const float* w3   = (const float*)d_in[11];
    const float* b3   = (const float*)d_in[12];
    float* out = (float*)d_out;

    // smem sizes
    const int smem_pre64  = 2*64*128*4;                 // 64 KB
    const int smem_pre128 = 2*128*128*4;                // 128 KB
    const int smem_edge2  = (128*132 + 40*128 + 256 + 128)*4 + 40*4;  // ~89.8 KB
    const int smem_fgemm  = (64*256 + 64*68)*4;         // ~81 KB

    cudaFuncSetAttribute((const void*)precomp_kernel<64>,  cudaFuncAttributeMaxDynamicSharedMemorySize, smem_pre64);
    cudaFuncSetAttribute((const void*)precomp_kernel<128>, cudaFuncAttributeMaxDynamicSharedMemorySize, smem_pre128);
    cudaFuncSetAttribute((const void*)edge2_kernel,        cudaFuncAttributeMaxDynamicSharedMemorySize, smem_edge2);
    cudaFuncSetAttribute((const void*)fgemm_kernel,        cudaFuncAttributeMaxDynamicSharedMemorySize, smem_fgemm);

    void *p_h, *p_hsq, *p_xsq, *p_idx1, *p_idx2, *p_A1, *p_C1, *p_cat, *p_A3, *p_C3, *p_w3t;
    cudaGetSymbolAddress(&p_h,    d_h);
    cudaGetSymbolAddress(&p_hsq,  d_hsq);
    cudaGetSymbolAddress(&p_xsq,  d_xsq);
    cudaGetSymbolAddress(&p_idx1, d_idx1);
    cudaGetSymbolAddress(&p_idx2, d_idx2);
    cudaGetSymbolAddress(&p_A1,   d_A1);
    cudaGetSymbolAddress(&p_C1,   d_C1);
    cudaGetSymbolAddress(&p_cat,  d_cat);
    cudaGetSymbolAddress(&p_A3,   d_A3);
    cudaGetSymbolAddress(&p_C3,   d_C3);
    cudaGetSymbolAddress(&p_w3t,  d_w3t);

    // 1. MLP: x -> h (B,N,64) + |h|^2, |x|^2
    mlp_kernel<<<NP/256, 256>>>(x, w1, b1, w2, b2);

    // 2. KNNs
    knn_kernel<64, 65><<<BB*(NN/32), 1024>>>((const float*)p_h, (const float*)p_hsq, (int*)p_idx1);
    knn_kernel<3, 4><<<BB*(NN/32), 1024>>>(x, (const float*)p_xsq, (int*)p_idx2);

    // 3. precompute A1/C1 from h with wdg1
    precomp_kernel<64><<<dim3(64, 1), 128, smem_pre64>>>(
        (const float*)p_h, 64, 0, wdg1, bdg1, (float*)p_A1, (float*)p_C1, 128);

    // 4. fused edge-conv 1+2 -> x1 (cat[:,0:128]), x2 (cat[:,128:256])
    edge2_kernel<<<256, 128, smem_edge2>>>(
        (const float*)p_A1, (const float*)p_C1, (const int*)p_idx1, wdg2, bdg2, (float*)p_cat);

    // 5. precompute A3/C3 from x2 with wsn1
    precomp_kernel<128><<<dim3(64, 2), 128, smem_pre128>>>(
        (const float*)p_cat, 512, 128, wsn1, bsn1, (float*)p_A3, (float*)p_C3, 256);

    // 6. edge-conv 3 -> x3 (cat[:,256:512])
    edge3_kernel<<<512, 256>>>((const float*)p_A3, (const float*)p_C3, (const int*)p_idx2, (float*)p_cat);

    // 7. final conv (GEMM 1024x512 over 32768 points)
    transpose_w3<<<(512*1024)/256, 256>>>(w3, (float*)p_w3t);
    fgemm_kernel<<<dim3(NP/64, 4), 256, smem_fgemm>>>(
        (const float*)p_cat, (const float*)p_w3t, b3, out);
}

// round 2
// speedup vs baseline: 1.9078x; 1.9078x over previous
#include <cuda_runtime.h>
#include <cstdint>

#define BB 8
#define NN 4096
#define NP (BB*NN)
#define KK 20

typedef unsigned long long ull;

__device__ __forceinline__ ull pk2(float a, float b){ ull r; asm("mov.b64 %0, {%1,%2};" : "=l"(r) : "f"(a), "f"(b)); return r; }
__device__ __forceinline__ ull fma2(ull a, ull b, ull c){ ull d; asm("fma.rn.f32x2 %0, %1, %2, %3;" : "=l"(d) : "l"(a), "l"(b), "l"(c)); return d; }
__device__ __forceinline__ void upk(ull v, float& a, float& b){ asm("mov.b64 {%0,%1}, %2;" : "=f"(a), "=f"(b) : "l"(v)); }

// ---------------- scratch -------------------------------------------------------
__device__ float d_h[NP*64];
__device__ float d_hsq[NP];
__device__ float d_xsq[NP];
__device__ int   d_idx1[NP*KK];
__device__ int   d_idx2[NP*KK];
__device__ float d_A1[NP*128];
__device__ float d_C1[NP*128];
__device__ float d_cat[(size_t)NP*512];   // x1 | x2 | x3
__device__ float d_A3[(size_t)NP*256];
__device__ float d_C3[(size_t)NP*256];
__device__ float d_w3t[512*1024];

// ---------------- kernel 1: 3->64->64 MLP + squared norms ------------------------
__global__ __launch_bounds__(256) void mlp_kernel(
    const float* __restrict__ x, const float* __restrict__ w1, const float* __restrict__ b1,
    const float* __restrict__ w2, const float* __restrict__ b2)
{
    __shared__ float w1s[192], b1s[64], b2s[64], w2s[4096];
    int t = threadIdx.x;
    for (int i = t; i < 192; i += 256) w1s[i] = w1[i];
    if (t < 64) { b1s[t] = b1[t]; b2s[t] = b2[t]; }
    for (int i = t; i < 4096; i += 256) w2s[i] = w2[i];
    __syncthreads();
    int pt = blockIdx.x * 256 + t;
    float x0 = x[pt*3+0], x1 = x[pt*3+1], x2 = x[pt*3+2];
    d_xsq[pt] = x0*x0 + x1*x1 + x2*x2;
    float h1[64];
#pragma unroll
    for (int o = 0; o < 64; o++) {
        float a = b1s[o] + w1s[o*3]*x0 + w1s[o*3+1]*x1 + w1s[o*3+2]*x2;
        h1[o] = fmaxf(a, 0.f);
    }
    float sq = 0.f;
#pragma unroll 2
    for (int o = 0; o < 64; o++) {
        float a = b2s[o];
#pragma unroll
        for (int c = 0; c < 64; c++) a += w2s[o*64+c] * h1[c];
        a = fmaxf(a, 0.f);
        d_h[(size_t)pt*64 + o] = a;
        sq += a*a;
    }
    d_hsq[pt] = sq;
}

// ---------------- kernel 2: tiled KNN (64 queries/block, 64-cand tiles) ----------
// dist = 2*dot - |q|^2 - |c|^2 ; keep 20 largest; tie-break smaller index.
__device__ __forceinline__ void tkins(float d, int id, float* vals, int* ids,
                                      float& minv, int& minp)
{
    if (d > minv) {
        vals[minp] = d; ids[minp] = id;
        minv = vals[0]; minp = 0;
#pragma unroll
        for (int r = 1; r < KK; r++) if (vals[r] < minv) { minv = vals[r]; minp = r; }
    }
}

template<int C>
__global__ __launch_bounds__(256) void knn2_kernel(
    const float* __restrict__ data, const float* __restrict__ sq, int* __restrict__ out)
{
    const int QT = 64, CT = 64;
    extern __shared__ float km[];
    float* qsT = km;                    // [C][68]
    float* csT = qsT + C*68;            // [C][68]
    float* ds  = csT + C*68;            // [64][68]
    float* qxx = ds + 64*68;            // [64]
    float* cxx = qxx + 64;              // [64]

    int b  = blockIdx.x / (NN/QT);
    int q0 = (blockIdx.x % (NN/QT)) * QT;
    int t = threadIdx.x;
    int tq = t >> 4, tc = t & 15;       // phase-A mapping
    int qq = t >> 2, s = t & 3;         // phase-B mapping

    for (int i = t; i < QT*C; i += 256) {
        int q = i / C, d = i - q*C;
        qsT[d*68 + q] = data[((size_t)(b*NN + q0 + q))*C + d];
    }
    if (t < QT) qxx[t] = sq[b*NN + q0 + t];

    float vals[KK]; int ids[KK];
#pragma unroll
    for (int r = 0; r < KK; r++) { vals[r] = -3.4e38f; ids[r] = 0x7fffffff; }
    float minv = -3.4e38f; int minp = 0;

    for (int tile = 0; tile < NN/CT; tile++) {
        __syncthreads();
        for (int i = t; i < CT*C; i += 256) {
            int cth = i / C, d = i - cth*C;
            csT[d*68 + cth] = data[((size_t)(b*NN + tile*CT + cth))*C + d];
        }
        if (t < CT) cxx[t] = sq[b*NN + tile*CT + t];
        __syncthreads();

        // phase A: 4q x 4c register tile, f32x2 over candidate pairs
        ull acc[4][2];
#pragma unroll
        for (int i = 0; i < 4; i++) { acc[i][0] = 0ull; acc[i][1] = 0ull; }
#pragma unroll 4
        for (int k = 0; k < C; k++) {
            float4 qv = *(const float4*)&qsT[k*68 + tq*4];
            float4 cv = *(const float4*)&csT[k*68 + tc*4];
            ull c01 = pk2(cv.x, cv.y), c23 = pk2(cv.z, cv.w);
            ull q0p = pk2(qv.x, qv.x), q1p = pk2(qv.y, qv.y);
            ull q2p = pk2(qv.z, qv.z), q3p = pk2(qv.w, qv.w);
            acc[0][0] = fma2(q0p, c01, acc[0][0]); acc[0][1] = fma2(q0p, c23, acc[0][1]);
            acc[1][0] = fma2(q1p, c01, acc[1][0]); acc[1][1] = fma2(q1p, c23, acc[1][1]);
            acc[2][0] = fma2(q2p, c01, acc[2][0]); acc[2][1] = fma2(q2p, c23, acc[2][1]);
            acc[3][0] = fma2(q3p, c01, acc[3][0]); acc[3][1] = fma2(q3p, c23, acc[3][1]);
        }
        float cx0 = cxx[tc*4], cx1 = cxx[tc*4+1], cx2 = cxx[tc*4+2], cx3 = cxx[tc*4+3];
#pragma unroll
        for (int i = 0; i < 4; i++) {
            float qx = qxx[tq*4 + i];
            float d0, d1, d2, d3;
            upk(acc[i][0], d0, d1); upk(acc[i][1], d2, d3);
            float4 r;
            r.x = 2.f*d0 - qx - cx0; r.y = 2.f*d1 - qx - cx1;
            r.z = 2.f*d2 - qx - cx2; r.w = 2.f*d3 - qx - cx3;
            *(float4*)&ds[(tq*4 + i)*68 + tc*4] = r;
        }
        __syncthreads();

        // phase B: each thread scans 16 candidates of its query
        const float* row = &ds[qq*68 + s*16];
        int base = tile*CT + s*16;
#pragma unroll
        for (int c4 = 0; c4 < 4; c4++) {
            float4 v = *(const float4*)&row[c4*4];
            tkins(v.x, base + c4*4 + 0, vals, ids, minv, minp);
            tkins(v.y, base + c4*4 + 1, vals, ids, minv, minp);
            tkins(v.z, base + c4*4 + 2, vals, ids, minv, minp);
            tkins(v.w, base + c4*4 + 3, vals, ids, minv, minp);
        }
    }

    // sort lane-local list desc by (val, idx asc)
#pragma unroll 1
    for (int i = 1; i < KK; i++) {
        float v = vals[i]; int id = ids[i]; int j = i - 1;
        while (j >= 0 && (vals[j] < v || (vals[j] == v && ids[j] > id))) {
            vals[j+1] = vals[j]; ids[j+1] = ids[j]; j--;
        }
        vals[j+1] = v; ids[j+1] = id;
    }
    // merge across the 4 s-threads of each query (4-lane groups within warp)
    int ptr = 0;
#pragma unroll 1
    for (int r = 0; r < KK; r++) {
        float v = (ptr < KK) ? vals[ptr] : -3.4e38f;
        int  id = (ptr < KK) ? ids[ptr]  : 0x7fffffff;
        int  sl = s;
#pragma unroll
        for (int off = 1; off <= 2; off <<= 1) {
            float ov = __shfl_xor_sync(0xffffffffu, v, off);
            int  oid = __shfl_xor_sync(0xffffffffu, id, off);
            int  osl = __shfl_xor_sync(0xffffffffu, sl, off);
            if (ov > v || (ov == v && oid < id)) { v = ov; id = oid; sl = osl; }
        }
        if (sl == s) ptr++;
        if (s == 0) out[((size_t)(b*NN + q0 + qq))*KK + r] = id;
    }
}

// ---------------- kernel 3: precompute A = Wa*in, C = (Wb-Wa)*in + bias ----------
template<int CIN>
__global__ __launch_bounds__(128) void precomp_kernel(
    const float* __restrict__ in, int instride, int inoff,
    const float* __restrict__ W, const float* __restrict__ bias,
    float* __restrict__ A, float* __restrict__ Cc, int Cout)
{
    extern __shared__ float sm[];
    float* wa = sm;               // [CIN][128]
    float* wd = sm + CIN*128;     // [CIN][128]
    __shared__ float inv[4*CIN];
    int t = threadIdx.x;
    int o0 = blockIdx.y * 128;
    int o  = o0 + t;
    for (int i = t; i < 128*2*CIN; i += 128) {
        int oo = i / (2*CIN), c = i - oo*(2*CIN);
        float v = W[(size_t)o0*2*CIN + i];
        if (c < CIN) wa[c*128 + oo] = v; else wd[(c-CIN)*128 + oo] = v;
    }
    __syncthreads();
    for (int c = 0; c < CIN; c++) wd[c*128 + t] -= wa[c*128 + t];
    float bo = bias[o];
    __syncthreads();

    int ppb = NP / gridDim.x;
    int pt0 = blockIdx.x * ppb;
    for (int g = 0; g < ppb; g += 4) {
        __syncthreads();
        for (int i = t; i < 4*CIN; i += 128) {
            int p = i / CIN, c = i - p*CIN;
            inv[i] = in[(size_t)(pt0 + g + p)*instride + inoff + c];
        }
        __syncthreads();
        float a0=0,a1=0,a2=0,a3=0, c0=bo,c1=bo,c2=bo,c3=bo;
        for (int c = 0; c < CIN; c++) {
            float va = wa[c*128 + t], vd = wd[c*128 + t];
            float v0 = inv[c], v1 = inv[CIN+c], v2 = inv[2*CIN+c], v3 = inv[3*CIN+c];
            a0 += va*v0; a1 += va*v1; a2 += va*v2; a3 += va*v3;
            c0 += vd*v0; c1 += vd*v1; c2 += vd*v2; c3 += vd*v3;
        }
        A [(size_t)(pt0+g+0)*Cout + o] = a0;  Cc[(size_t)(pt0+g+0)*Cout + o] = c0;
        A [(size_t)(pt0+g+1)*Cout + o] = a1;  Cc[(size_t)(pt0+g+1)*Cout + o] = c1;
        A [(size_t)(pt0+g+2)*Cout + o] = a2;  Cc[(size_t)(pt0+g+2)*Cout + o] = c2;
        A [(size_t)(pt0+g+3)*Cout + o] = a3;  Cc[(size_t)(pt0+g+3)*Cout + o] = c3;
    }
}

// ---------------- kernel 4: fused edge-conv1 (decomposed) + edge-conv2 GEMM ------
// 4 points (80 pk) per iter, 256 threads, 4o x 10pk register tile with f32x2.
__global__ __launch_bounds__(256) void edge2_kernel(
    const float* __restrict__ A1, const float* __restrict__ C1,
    const int* __restrict__ idx, const float* __restrict__ w2,
    const float* __restrict__ b2, float* __restrict__ cat)
{
    extern __shared__ float sm[];
    float* ws  = sm;                  // [128c][128o]  (transposed)
    float* gs  = ws + 128*128;        // [80pk][128c]  relu'd g
    float* c1s = gs + 80*128;         // [4][128]
    float* px  = c1s + 4*128;         // [8pg][128o]
    float* b2s = px + 8*128;          // [128]
    int*   ixs = (int*)(b2s + 128);   // [80]
    int t = threadIdx.x;
    for (int i = t; i < 128*128; i += 256) { int o = i >> 7, c = i & 127; ws[c*128 + o] = w2[i]; }
    if (t < 128) b2s[t] = b2[t];
    __syncthreads();

    int og = t & 31, pg = t >> 5;      // GEMM mapping: o = og*4..og*4+3, pk = pg*10..+9
    int cc = t & 127, hh = t >> 7;     // gather/combine mapping

    int ppb = (NP/4) / gridDim.x;
    for (int pr = 0; pr < ppb; pr++) {
        int pt0 = (blockIdx.x * ppb + pr) * 4;
        int b = pt0 / NN;
        __syncthreads();
        for (int i = t; i < 512; i += 256) c1s[i] = C1[(size_t)pt0*128 + i];
        if (t < 80) { int p = t / 20, k = t - p*20; ixs[t] = idx[(size_t)(pt0+p)*KK + k]; }
        __syncthreads();
        // gather + conv1(decomposed) + relu
        for (int pk = hh; pk < 80; pk += 2) {
            int p = pk / 20;
            float a = A1[((size_t)(b*NN + ixs[pk]))*128 + cc];
            gs[pk*128 + cc] = fmaxf(a + c1s[p*128 + cc], 0.f);
        }
        __syncthreads();
        // conv2 GEMM: acc[(o,o+1),(o+2,o+3)][10 pk]
        ull acc[2][10];
        {
            ull b01 = pk2(b2s[og*4],   b2s[og*4+1]);
            ull b23 = pk2(b2s[og*4+2], b2s[og*4+3]);
#pragma unroll
            for (int j = 0; j < 10; j++) { acc[0][j] = b01; acc[1][j] = b23; }
        }
#pragma unroll 2
        for (int c = 0; c < 128; c++) {
            float4 wv = *(const float4*)&ws[c*128 + og*4];
            ull w01 = pk2(wv.x, wv.y), w23 = pk2(wv.z, wv.w);
            const float* gcol = &gs[(pg*10)*128 + c];
#pragma unroll
            for (int j = 0; j < 10; j++) {
                ull gg = pk2(gcol[j*128], gcol[j*128]);
                acc[0][j] = fma2(w01, gg, acc[0][j]);
                acc[1][j] = fma2(w23, gg, acc[1][j]);
            }
        }
        // per-thread max over its 10 pk, per o
        float m0=-3.4e38f, m1=-3.4e38f, m2=-3.4e38f, m3=-3.4e38f;
#pragma unroll
        for (int j = 0; j < 10; j++) {
            float v0, v1, v2, v3;
            upk(acc[0][j], v0, v1); upk(acc[1][j], v2, v3);
            m0 = fmaxf(m0, v0); m1 = fmaxf(m1, v1);
            m2 = fmaxf(m2, v2); m3 = fmaxf(m3, v3);
        }
        px[pg*128 + og*4+0] = m0; px[pg*128 + og*4+1] = m1;
        px[pg*128 + og*4+2] = m2; px[pg*128 + og*4+3] = m3;
        __syncthreads();
        // combine: thread handles 2 points (channels = cc)
#pragma unroll
        for (int pi = 0; pi < 2; pi++) {
            int p = hh*2 + pi;
            float x2 = fmaxf(px[(2*p)*128 + cc], px[(2*p+1)*128 + cc]);
            float x1 = -3.4e38f;
#pragma unroll 4
            for (int k = 0; k < 20; k++) x1 = fmaxf(x1, gs[(p*20 + k)*128 + cc]);
            cat[(size_t)(pt0+p)*512 + cc]       = x1;
            cat[(size_t)(pt0+p)*512 + 128 + cc] = fmaxf(x2, 0.f);
        }
    }
}

// ---------------- kernel 5: edge-conv3 (gather+add+max) --------------------------
__global__ __launch_bounds__(256) void edge3_kernel(
    const float* __restrict__ A3, const float* __restrict__ C3,
    const int* __restrict__ idx, float* __restrict__ cat)
{
    __shared__ float c3s[256];
    __shared__ int ixs[KK];
    int t = threadIdx.x;
    int ppb = NP / gridDim.x;
    for (int g = 0; g < ppb; g++) {
        int pt = blockIdx.x * ppb + g;
        __syncthreads();
        c3s[t] = C3[(size_t)pt*256 + t];
        if (t < KK) ixs[t] = idx[(size_t)pt*KK + t];
        __syncthreads();
        int b = pt / NN;
        float m = -3.4e38f;
#pragma unroll 4
        for (int k = 0; k < KK; k++) {
            float a = A3[((size_t)(b*NN + ixs[k]))*256 + t];
            m = fmaxf(m, a + c3s[t]);
        }
        cat[(size_t)pt*512 + 256 + t] = fmaxf(m, 0.f);
    }
}

// ---------------- kernel 6: weight transpose -------------------------------------
__global__ __launch_bounds__(256) void transpose_w3(const float* __restrict__ w3, float* __restrict__ w3t)
{
    int i = blockIdx.x * 256 + threadIdx.x;
    int o = i >> 9, c = i & 511;
    w3t[c*1024 + o] = w3[i];
}

// ---------------- kernel 7: final GEMM 1024x512, 8x8 reg tile, f32x2 -------------
__global__ __launch_bounds__(256) void fgemm_kernel(
    const float* __restrict__ cat, const float* __restrict__ w3t,
    const float* __restrict__ b3, float* __restrict__ out)
{
    __shared__ float Ws[32*128];      // [k][o]
    __shared__ float Xs[32*129];      // [k][p] pad 129 (conflict-free staging)
    int t = threadIdx.x;
    int o0 = blockIdx.y * 128;
    int n0 = blockIdx.x * 128;
    int to = t & 15, tp = t >> 4;     // o = {4to..4to+3, 64+4to..}, p = tp + 16j

    ull acc[4][8];
#pragma unroll
    for (int wh = 0; wh < 2; wh++)
#pragma unroll
        for (int u = 0; u < 2; u++) {
            int ol = o0 + 64*wh + 4*to + 2*u;
            ull bb = pk2(b3[ol], b3[ol+1]);
#pragma unroll
            for (int j = 0; j < 8; j++) acc[wh*2+u][j] = bb;
        }

    for (int kc = 0; kc < 16; kc++) {
        __syncthreads();
        for (int i = t; i < 32*128; i += 256)
            Ws[i] = w3t[(size_t)(kc*32 + (i >> 7))*1024 + o0 + (i & 127)];
        for (int i = t; i < 32*128; i += 256) {
            int p = i >> 5, k = i & 31;
            Xs[k*129 + p] = cat[(size_t)(n0 + p)*512 + kc*32 + k];
        }
        __syncthreads();
#pragma unroll 4
        for (int k = 0; k < 32; k++) {
            float4 w0 = *(const float4*)&Ws[k*128 + 4*to];
            float4 w1 = *(const float4*)&Ws[k*128 + 64 + 4*to];
            ull w00 = pk2(w0.x, w0.y), w01 = pk2(w0.z, w0.w);
            ull w10 = pk2(w1.x, w1.y), w11 = pk2(w1.z, w1.w);
            const float* xr = &Xs[k*129 + tp];
#pragma unroll
            for (int j = 0; j < 8; j++) {
                float xv = xr[16*j];
                ull xx = pk2(xv, xv);
                acc[0][j] = fma2(w00, xx, acc[0][j]);
                acc[1][j] = fma2(w01, xx, acc[1][j]);
                acc[2][j] = fma2(w10, xx, acc[2][j]);
                acc[3][j] = fma2(w11, xx, acc[3][j]);
            }
        }
    }
    int b = n0 >> 12, n = n0 & 4095;
#pragma unroll
    for (int wh = 0; wh < 2; wh++)
#pragma unroll
        for (int u = 0; u < 2; u++) {
            int ol = o0 + 64*wh + 4*to + 2*u;
#pragma unroll
            for (int j = 0; j < 8; j++) {
                int p = tp + 16*j;
                float v0, v1;
                upk(acc[wh*2+u][j], v0, v1);
                out[((size_t)(b*1024 + ol  ))*NN + n + p] = fmaxf(v0, 0.f);
                out[((size_t)(b*1024 + ol+1))*NN + n + p] = fmaxf(v1, 0.f);
            }
        }
}

// ---------------------------------------------------------------------------------
extern "C" void kernel_launch(void* const* d_in, const int* in_sizes, int n_in,
                              void* d_out, int out_size)
{
    const float* x    = (const float*)d_in[0];
    const float* w1   = (const float*)d_in[1];
    const float* b1   = (const float*)d_in[2];
    const float* w2   = (const float*)d_in[3];
    const float* b2   = (const float*)d_in[4];
    const float* wdg1 = (const float*)d_in[5];
    const float* bdg1 = (const float*)d_in[6];
    const float* wdg2 = (const float*)d_in[7];
    const float* bdg2 = (const float*)d_in[8];
    const float* wsn1 = (const float*)d_in[9];
    const float* bsn1 = (const float*)d_in[10];
    const float* w3   = (const float*)d_in[11];
    const float* b3   = (const float*)d_in[12];
    float* out = (float*)d_out;

    const int smem_knn64 = (64*68*2 + 64*68 + 128) * 4;
    const int smem_knn3  = (3*68*2 + 64*68 + 128) * 4;
    const int smem_pre64  = 2*64*128*4;
    const int smem_pre128 = 2*128*128*4;
    const int smem_edge2  = (128*128 + 80*128 + 4*128 + 8*128 + 128)*4 + 80*4;

    cudaFuncSetAttribute((const void*)knn2_kernel<64>,     cudaFuncAttributeMaxDynamicSharedMemorySize, smem_knn64);
    cudaFuncSetAttribute((const void*)knn2_kernel<3>,      cudaFuncAttributeMaxDynamicSharedMemorySize, smem_knn3);
    cudaFuncSetAttribute((const void*)precomp_kernel<64>,  cudaFuncAttributeMaxDynamicSharedMemorySize, smem_pre64);
    cudaFuncSetAttribute((const void*)precomp_kernel<128>, cudaFuncAttributeMaxDynamicSharedMemorySize, smem_pre128);
    cudaFuncSetAttribute((const void*)edge2_kernel,        cudaFuncAttributeMaxDynamicSharedMemorySize, smem_edge2);

    void *p_h, *p_hsq, *p_xsq, *p_idx1, *p_idx2, *p_A1, *p_C1, *p_cat, *p_A3, *p_C3, *p_w3t;
    cudaGetSymbolAddress(&p_h,    d_h);
    cudaGetSymbolAddress(&p_hsq,  d_hsq);
    cudaGetSymbolAddress(&p_xsq,  d_xsq);
    cudaGetSymbolAddress(&p_idx1, d_idx1);
    cudaGetSymbolAddress(&p_idx2, d_idx2);
    cudaGetSymbolAddress(&p_A1,   d_A1);
    cudaGetSymbolAddress(&p_C1,   d_C1);
    cudaGetSymbolAddress(&p_cat,  d_cat);
    cudaGetSymbolAddress(&p_A3,   d_A3);
    cudaGetSymbolAddress(&p_C3,   d_C3);
    cudaGetSymbolAddress(&p_w3t,  d_w3t);

    mlp_kernel<<<NP/256, 256>>>(x, w1, b1, w2, b2);

    knn2_kernel<64><<<BB*(NN/64), 256, smem_knn64>>>((const float*)p_h, (const float*)p_hsq, (int*)p_idx1);
    knn2_kernel<3><<<BB*(NN/64), 256, smem_knn3>>>(x, (const float*)p_xsq, (int*)p_idx2);

    precomp_kernel<64><<<dim3(512, 1), 128, smem_pre64>>>(
        (const float*)p_h, 64, 0, wdg1, bdg1, (float*)p_A1, (float*)p_C1, 128);

    edge2_kernel<<<256, 256, smem_edge2>>>(
        (const float*)p_A1, (const float*)p_C1, (const int*)p_idx1, wdg2, bdg2, (float*)p_cat);

    precomp_kernel<128><<<dim3(256, 2), 128, smem_pre128>>>(
        (const float*)p_cat, 512, 128, wsn1, bsn1, (float*)p_A3, (float*)p_C3, 256);

    edge3_kernel<<<512, 256>>>((const float*)p_A3, (const float*)p_C3, (const int*)p_idx2, (float*)p_cat);

    transpose_w3<<<(512*1024)/256, 256>>>(w3, (float*)p_w3t);
    fgemm_kernel<<<dim3(NP/128, 8), 256>>>(
        (const float*)p_cat, (const float*)p_w3t, b3, out);
}